// round 3
// baseline (speedup 1.0000x reference)
// R2: resubmission of R1 (infra failure, no signal) — grid=25 attention tiles.
#include <cuda_runtime.h>

// ---------------------------------------------------------------------------
// Problem constants
//   x: (2, 8192, 512) fp32;  w_qkv: (512,1536);  b_qkv: (1536,)
//   w_out: (512,512);  b_out: (512,)  -> out (2, 8192, 512) fp32
//   H=16 heads, D=32.  Segments [0,1024) r=1, [1024,3072) r=2,
//   [3072,7168) r=4, [7168,8192) r=8, each Hilbert-permuted.
// ---------------------------------------------------------------------------

#define SEQ   8192
#define BATCH 2
#define EMB   512
#define NH    16
#define HD    32
#define QKVW  1536

// SCALE * log2(e): fold into q so softmax uses exp2
#define SCALE_L2E (0.17677669529663687f * 1.44269504088896340f)

// Scratch (static device globals; no allocation allowed)
__device__ float g_qkv[BATCH * SEQ * QKVW];   // 25.2M floats
__device__ float g_o[BATCH * SEQ * EMB];      // 8.4M floats
__device__ int   g_table[SEQ];                // gathered index lists

static __device__ __forceinline__ float ex2f(float x) {
    float y; asm("ex2.approx.f32 %0, %1;" : "=f"(y) : "f"(x)); return y;
}

// ---------------------------------------------------------------------------
// Hilbert index-table build.
// For segment seg with params (pos, L, r, side):
//   perm[i] = i-th value of {lin(d) : d in [0, side^2), lin(d) < L} in d-order
//   table[pos + (i%r)*g + i/r] = pos + perm[i],   g = L/r
// One block per segment, 1024 threads, block-wide scan for the filtered case.
// ---------------------------------------------------------------------------
__device__ __forceinline__ int hilbert_lin(int side, int d) {
    int x = 0, y = 0, t = d;
    for (int s = 1; s < side; s <<= 1) {
        int rx = (t >> 1) & 1;
        int ry = (t ^ rx) & 1;
        if (ry == 0) {
            if (rx == 1) { x = s - 1 - x; y = s - 1 - y; }
            int tmp = x; x = y; y = tmp;
        }
        x += s * rx;
        y += s * ry;
        t >>= 2;
    }
    return y * side + x;
}

__global__ void build_table_kernel() {
    const int posA[4]  = {0, 1024, 3072, 7168};
    const int LA[4]    = {1024, 2048, 4096, 1024};
    const int rA[4]    = {1, 2, 4, 8};
    const int sideA[4] = {32, 64, 64, 32};

    int seg  = blockIdx.x;
    int pos  = posA[seg], L = LA[seg], r = rA[seg], side = sideA[seg];
    int side2 = side * side;
    int g    = L / r;
    int t    = threadIdx.x;
    int chunk = side2 >> 10;          // 1 or 4 d-values per thread

    int lin[4];
    int cnt = 0;
    for (int c = 0; c < chunk; c++) {
        lin[c] = hilbert_lin(side, t * chunk + c);
        if (lin[c] < L) cnt++;
    }

    __shared__ int sc[1024];
    sc[t] = cnt;
    __syncthreads();
    for (int off = 1; off < 1024; off <<= 1) {
        int v = (t >= off) ? sc[t - off] : 0;
        __syncthreads();
        sc[t] += v;
        __syncthreads();
    }
    int i = sc[t] - cnt;   // exclusive prefix of valid count

    for (int c = 0; c < chunk; c++) {
        if (lin[c] < L) {
            int res = i % r;
            int j   = i / r;
            g_table[pos + res * g + j] = pos + lin[c];
            i++;
        }
    }
}

// ---------------------------------------------------------------------------
// Zero the attention output scratch (positions not owned by a head stay 0)
// ---------------------------------------------------------------------------
__global__ void zero_kernel() {
    int i = (blockIdx.x * 256 + threadIdx.x) * 4;
    *(float4*)(g_o + i) = make_float4(0.f, 0.f, 0.f, 0.f);
}

// ---------------------------------------------------------------------------
// SGEMM with bias: C[M,N] = A[M,K] @ B[K,N] + bias[N]  (all row-major, fp32)
// 64x64x16 tile, 256 threads, 4x4 microtile, transposed+padded A smem tile.
// M,N,K are exact multiples of the tile — no bounds checks.
// ---------------------------------------------------------------------------
__global__ void __launch_bounds__(256) sgemm_bias_kernel(
    const float* __restrict__ A, const float* __restrict__ Bm,
    const float* __restrict__ bias, float* __restrict__ C,
    int M, int N, int K)
{
    __shared__ float As[16][68];   // [k][m], 68-pad
    __shared__ float Bs[16][64];   // [k][n]

    int t  = threadIdx.x;
    int bm = blockIdx.y * 64;
    int bn = blockIdx.x * 64;
    int tr = t >> 4;               // 0..15
    int tc = t & 15;               // 0..15

    float acc[4][4];
#pragma unroll
    for (int i = 0; i < 4; i++)
#pragma unroll
        for (int j = 0; j < 4; j++) acc[i][j] = 0.f;

    int arow = t >> 2;             // 0..63
    int ak4  = (t & 3) << 2;       // 0,4,8,12
    int brow = t >> 4;             // 0..15
    int bc4  = (t & 15) << 2;      // 0..60

    const float* Aptr = A + (size_t)(bm + arow) * K + ak4;
    const float* Bptr = Bm + (size_t)brow * N + bn + bc4;

    for (int k0 = 0; k0 < K; k0 += 16) {
        float4 av = *(const float4*)(Aptr + k0);
        As[ak4 + 0][arow] = av.x;
        As[ak4 + 1][arow] = av.y;
        As[ak4 + 2][arow] = av.z;
        As[ak4 + 3][arow] = av.w;
        *(float4*)&Bs[brow][bc4] = *(const float4*)(Bptr + (size_t)k0 * N);
        __syncthreads();

#pragma unroll
        for (int kk = 0; kk < 16; kk++) {
            float4 a = *(const float4*)&As[kk][tr << 2];
            float4 b = *(const float4*)&Bs[kk][tc << 2];
            float ar[4] = {a.x, a.y, a.z, a.w};
            float br[4] = {b.x, b.y, b.z, b.w};
#pragma unroll
            for (int i = 0; i < 4; i++)
#pragma unroll
                for (int j = 0; j < 4; j++)
                    acc[i][j] = fmaf(ar[i], br[j], acc[i][j]);
        }
        __syncthreads();
    }

    float4 bb = *(const float4*)(bias + bn + (tc << 2));
    float bbr[4] = {bb.x, bb.y, bb.z, bb.w};
#pragma unroll
    for (int i = 0; i < 4; i++) {
        int row = bm + (tr << 2) + i;
        float4 ov;
        ov.x = acc[i][0] + bbr[0];
        ov.y = acc[i][1] + bbr[1];
        ov.z = acc[i][2] + bbr[2];
        ov.w = acc[i][3] + bbr[3];
        *(float4*)(C + (size_t)row * N + bn + (tc << 2)) = ov;
    }
}

// ---------------------------------------------------------------------------
// Flash-style attention over a gathered index list.
// grid = (25 q-tiles, 16 heads, 2 batch), block = 128 threads.
//   seg0: tiles 0..7   (g=1024), seg1: 8..15 (g=1024),
//   seg2: tiles 16..23 (g=1024), seg3: 24    (g=128).
// One thread owns one q-row: q[32] and acc[32] live entirely in registers.
// K/V streamed through smem in 64-row tiles; inner loop reads k_j/v_j as
// broadcast LDS.128. Streaming online softmax (rescale only on new max).
// ---------------------------------------------------------------------------
__global__ void __launch_bounds__(128) attn_kernel() {
    int x = blockIdx.x;
    int h = blockIdx.y;
    int b = blockIdx.z;

    int seg, tile;
    if      (x < 8)  { seg = 0; tile = x;      }
    else if (x < 16) { seg = 1; tile = x - 8;  }
    else if (x < 24) { seg = 2; tile = x - 16; }
    else             { seg = 3; tile = 0;      }

    int g, base;
    if      (seg == 0) { g = 1024; base = 0; }
    else if (seg == 1) { g = 1024; base = 1024 + (h & 1) * 1024; }
    else if (seg == 2) { g = 1024; base = 3072 + (h & 3) * 1024; }
    else               { g = 128;  base = 7168 + (h & 7) * 128;  }

    int t  = threadIdx.x;
    int gq = g_table[base + tile * 128 + t];

    const float* qp = g_qkv + (size_t)(b * SEQ + gq) * QKVW + h * HD;
    float q[32], acc[32];
#pragma unroll
    for (int i = 0; i < 8; i++) {
        float4 v = *(const float4*)(qp + i * 4);
        q[i * 4 + 0] = v.x * SCALE_L2E;
        q[i * 4 + 1] = v.y * SCALE_L2E;
        q[i * 4 + 2] = v.z * SCALE_L2E;
        q[i * 4 + 3] = v.w * SCALE_L2E;
    }
#pragma unroll
    for (int d = 0; d < 32; d++) acc[d] = 0.f;

    float m = -1e30f;
    float l = 0.f;

    __shared__ float Ks[64][32];
    __shared__ float Vs[64][32];

    for (int kt = 0; kt < g; kt += 64) {
        // cooperative gather of 64 K rows + 64 V rows (each row 128B)
#pragma unroll
        for (int i = 0; i < 4; i++) {
            int f4  = t + 128 * i;          // 0..511
            int row = f4 >> 3;
            int c4  = (f4 & 7) << 2;
            int kidx = g_table[base + kt + row];
            const float* src = g_qkv + (size_t)(b * SEQ + kidx) * QKVW + EMB + h * HD + c4;
            *(float4*)&Ks[row][c4] = *(const float4*)src;
            *(float4*)&Vs[row][c4] = *(const float4*)(src + EMB);
        }
        __syncthreads();

#pragma unroll 2
        for (int j = 0; j < 64; j++) {
            const float4* kr = (const float4*)Ks[j];
            float s0 = 0.f, s1 = 0.f, s2 = 0.f, s3 = 0.f;
#pragma unroll
            for (int i = 0; i < 8; i++) {
                float4 kv = kr[i];
                s0 = fmaf(q[i * 4 + 0], kv.x, s0);
                s1 = fmaf(q[i * 4 + 1], kv.y, s1);
                s2 = fmaf(q[i * 4 + 2], kv.z, s2);
                s3 = fmaf(q[i * 4 + 3], kv.w, s3);
            }
            float s  = (s0 + s1) + (s2 + s3);   // already includes SCALE*log2e
            float mn = fmaxf(m, s);
            float p  = ex2f(s - mn);
            if (mn > m) {                        // rare: new running max
                float corr = ex2f(m - mn);
                l *= corr;
#pragma unroll
                for (int d = 0; d < 32; d++) acc[d] *= corr;
                m = mn;
            }
            l += p;
            const float4* vr = (const float4*)Vs[j];
#pragma unroll
            for (int i = 0; i < 8; i++) {
                float4 vv = vr[i];
                acc[i * 4 + 0] = fmaf(p, vv.x, acc[i * 4 + 0]);
                acc[i * 4 + 1] = fmaf(p, vv.y, acc[i * 4 + 1]);
                acc[i * 4 + 2] = fmaf(p, vv.z, acc[i * 4 + 2]);
                acc[i * 4 + 3] = fmaf(p, vv.w, acc[i * 4 + 3]);
            }
        }
        __syncthreads();
    }

    float inv = 1.0f / l;
    float* op = g_o + (size_t)(b * SEQ + gq) * EMB + h * HD;
#pragma unroll
    for (int i = 0; i < 8; i++) {
        float4 ov;
        ov.x = acc[i * 4 + 0] * inv;
        ov.y = acc[i * 4 + 1] * inv;
        ov.z = acc[i * 4 + 2] * inv;
        ov.w = acc[i * 4 + 3] * inv;
        *(float4*)(op + i * 4) = ov;
    }
}

// ---------------------------------------------------------------------------
// Launch
// ---------------------------------------------------------------------------
extern "C" void kernel_launch(void* const* d_in, const int* in_sizes, int n_in,
                              void* d_out, int out_size) {
    const float* x     = (const float*)d_in[0];
    const float* w_qkv = (const float*)d_in[1];
    const float* b_qkv = (const float*)d_in[2];
    const float* w_out = (const float*)d_in[3];
    const float* b_out = (const float*)d_in[4];
    float* out = (float*)d_out;

    float* qkv_ptr = nullptr;
    float* o_ptr   = nullptr;
    cudaGetSymbolAddress((void**)&qkv_ptr, g_qkv);
    cudaGetSymbolAddress((void**)&o_ptr, g_o);

    // 1. index tables (cheap, idempotent)
    build_table_kernel<<<4, 1024>>>();

    // 2. qkv projection: (16384x512) @ (512x1536) + b
    {
        dim3 grid(QKVW / 64, (BATCH * SEQ) / 64);
        sgemm_bias_kernel<<<grid, 256>>>(x, w_qkv, b_qkv, qkv_ptr,
                                         BATCH * SEQ, QKVW, EMB);
    }

    // 3. zero attention output scratch
    zero_kernel<<<(BATCH * SEQ * EMB) / (4 * 256), 256>>>();

    // 4. dilated Hilbert attention (25 q-tiles x 16 heads x 2 batch)
    {
        dim3 grid(25, NH, BATCH);
        attn_kernel<<<grid, 128>>>();
    }

    // 5. output projection: (16384x512) @ (512x512) + b -> d_out
    {
        dim3 grid(EMB / 64, (BATCH * SEQ) / 64);
        sgemm_bias_kernel<<<grid, 256>>>(o_ptr, w_out, b_out, out,
                                         BATCH * SEQ, EMB, EMB);
    }
}

// round 7
// speedup vs baseline: 1.4368x; 1.4368x over previous
// R6: byte-identical resubmission of R5 (infra failure; kernel audited clean —
// all PTX features are sm_80+ baseline, valid on compute_100).
// R5: mma.sync (HMMA) bf16-split GEMMs — tcgen05 unavailable (toolchain targets
// compute_100, not sm_100a). 3-term split folded into K=1536 concat buffers.
#include <cuda_runtime.h>
#include <cuda_bf16.h>
#include <cstdint>

#define SEQ   8192
#define BATCH 2
#define EMB   512
#define NH    16
#define HD    32
#define QKVW  1536
#define MROWS (BATCH * SEQ)          // 16384
#define KCAT  1536                   // 3 x 512 split terms
#define ASTRIDE 40                   // padded smem row (bf16 elems)

#define SCALE_L2E (0.17677669529663687f * 1.44269504088896340f)

// ---------------------------------------------------------------------------
// Scratch (static device globals; no allocation allowed)
// ---------------------------------------------------------------------------
__device__ float g_qkv[MROWS * QKVW];              // fp32 qkv (attention input)
__device__ float g_o[MROWS * EMB];                 // fp32 attention output
__device__ int   g_table[SEQ];                     // gathered index lists

__device__ __nv_bfloat16 g_acat[MROWS * KCAT];     // [xhi | xhi | xlo]
__device__ __nv_bfloat16 g_ocat[MROWS * KCAT];     // [ohi | ohi | olo]
__device__ __nv_bfloat16 g_bq[QKVW * KCAT];        // w_qkv^T: [hi | lo | hi]
__device__ __nv_bfloat16 g_bo[EMB * KCAT];         // w_out^T: [hi | lo | hi]

static __device__ __forceinline__ float ex2f(float x) {
    float y; asm("ex2.approx.f32 %0, %1;" : "=f"(y) : "f"(x)); return y;
}

static __device__ __forceinline__ uint32_t smem_u32(const void* p) {
    uint32_t a;
    asm("{ .reg .u64 t; cvta.to.shared.u64 t, %1; cvt.u32.u64 %0, t; }" : "=r"(a) : "l"(p));
    return a;
}

static __device__ __forceinline__ void cp16(uint32_t s, const void* g) {
    asm volatile("cp.async.cg.shared.global [%0], [%1], 16;" :: "r"(s), "l"(g));
}
#define CP_COMMIT() asm volatile("cp.async.commit_group;" ::: "memory")
#define CP_WAIT(n)  asm volatile("cp.async.wait_group %0;" :: "n"(n) : "memory")

static __device__ __forceinline__ void ldmx4(uint32_t* r, uint32_t addr) {
    asm volatile("ldmatrix.sync.aligned.m8n8.x4.shared.b16 {%0,%1,%2,%3}, [%4];"
                 : "=r"(r[0]), "=r"(r[1]), "=r"(r[2]), "=r"(r[3]) : "r"(addr));
}

static __device__ __forceinline__ void mma16816(float* c, const uint32_t* a,
                                                uint32_t b0, uint32_t b1) {
    asm volatile(
        "mma.sync.aligned.m16n8k16.row.col.f32.bf16.bf16.f32 "
        "{%0,%1,%2,%3}, {%4,%5,%6,%7}, {%8,%9}, {%0,%1,%2,%3};"
        : "+f"(c[0]), "+f"(c[1]), "+f"(c[2]), "+f"(c[3])
        : "r"(a[0]), "r"(a[1]), "r"(a[2]), "r"(a[3]), "r"(b0), "r"(b1));
}

// ---------------------------------------------------------------------------
// Hilbert index-table build (unchanged)
// ---------------------------------------------------------------------------
__device__ __forceinline__ int hilbert_lin(int side, int d) {
    int x = 0, y = 0, t = d;
    for (int s = 1; s < side; s <<= 1) {
        int rx = (t >> 1) & 1;
        int ry = (t ^ rx) & 1;
        if (ry == 0) {
            if (rx == 1) { x = s - 1 - x; y = s - 1 - y; }
            int tmp = x; x = y; y = tmp;
        }
        x += s * rx;
        y += s * ry;
        t >>= 2;
    }
    return y * side + x;
}

__global__ void build_table_kernel() {
    const int posA[4]  = {0, 1024, 3072, 7168};
    const int LA[4]    = {1024, 2048, 4096, 1024};
    const int rA[4]    = {1, 2, 4, 8};
    const int sideA[4] = {32, 64, 64, 32};

    int seg = blockIdx.x;
    int pos = posA[seg], L = LA[seg], r = rA[seg], side = sideA[seg];
    int side2 = side * side;
    int g = L / r;
    int t = threadIdx.x;
    int chunk = side2 >> 10;

    int lin[4];
    int cnt = 0;
    for (int c = 0; c < chunk; c++) {
        lin[c] = hilbert_lin(side, t * chunk + c);
        if (lin[c] < L) cnt++;
    }

    __shared__ int sc[1024];
    sc[t] = cnt;
    __syncthreads();
    for (int off = 1; off < 1024; off <<= 1) {
        int v = (t >= off) ? sc[t - off] : 0;
        __syncthreads();
        sc[t] += v;
        __syncthreads();
    }
    int i = sc[t] - cnt;

    for (int c = 0; c < chunk; c++) {
        if (lin[c] < L) {
            int res = i % r;
            int j   = i / r;
            g_table[pos + res * g + j] = pos + lin[c];
            i++;
        }
    }
}

// ---------------------------------------------------------------------------
// fp32 [M][512] -> concat bf16 [M][1536] = [hi | hi | lo]
// ---------------------------------------------------------------------------
__global__ void split_cat_kernel(const float* __restrict__ in,
                                 __nv_bfloat16* __restrict__ cat) {
    int i4 = (blockIdx.x * 256 + threadIdx.x) * 4;
    int m = i4 >> 9;
    int j = i4 & 511;
    float4 v = *(const float4*)(in + i4);

    __nv_bfloat162 h0, h1, l0, l1;
    h0.x = __float2bfloat16(v.x);  h0.y = __float2bfloat16(v.y);
    h1.x = __float2bfloat16(v.z);  h1.y = __float2bfloat16(v.w);
    l0.x = __float2bfloat16(v.x - __bfloat162float(h0.x));
    l0.y = __float2bfloat16(v.y - __bfloat162float(h0.y));
    l1.x = __float2bfloat16(v.z - __bfloat162float(h1.x));
    l1.y = __float2bfloat16(v.w - __bfloat162float(h1.y));

    __nv_bfloat16* row = cat + (size_t)m * KCAT;
    *(__nv_bfloat162*)(row + j)          = h0;
    *(__nv_bfloat162*)(row + j + 2)      = h1;
    *(__nv_bfloat162*)(row + 512 + j)    = h0;
    *(__nv_bfloat162*)(row + 512 + j + 2)= h1;
    *(__nv_bfloat162*)(row + 1024 + j)   = l0;
    *(__nv_bfloat162*)(row + 1024 + j + 2)= l1;
}

// ---------------------------------------------------------------------------
// fp32 weight [K=512][N] -> transposed concat bf16 [N][1536] = [hi | lo | hi]
// ---------------------------------------------------------------------------
__global__ void transpose_split_cat_kernel(const float* __restrict__ in,
                                           __nv_bfloat16* __restrict__ cat, int N) {
    __shared__ float tile[32][33];
    int n0 = blockIdx.x * 32, k0 = blockIdx.y * 32;
    int tx = threadIdx.x, ty = threadIdx.y;
#pragma unroll
    for (int i = 0; i < 32; i += 8)
        tile[ty + i][tx] = in[(size_t)(k0 + ty + i) * N + n0 + tx];
    __syncthreads();
#pragma unroll
    for (int i = 0; i < 32; i += 8) {
        float v = tile[tx][ty + i];
        __nv_bfloat16 h = __float2bfloat16(v);
        __nv_bfloat16 l = __float2bfloat16(v - __bfloat162float(h));
        size_t o = (size_t)(n0 + ty + i) * KCAT + k0 + tx;
        cat[o]        = h;
        cat[o + 512]  = l;
        cat[o + 1024] = h;
    }
}

// ---------------------------------------------------------------------------
// Zero the attention output scratch
// ---------------------------------------------------------------------------
__global__ void zero_kernel() {
    int i = (blockIdx.x * 256 + threadIdx.x) * 4;
    *(float4*)(g_o + i) = make_float4(0.f, 0.f, 0.f, 0.f);
}

// ---------------------------------------------------------------------------
// HMMA GEMM:  C[M][N] = Acat[M][1536] · Bcat[N][1536]^T + bias[N]
// 128x128 tile, 256 thr (8 warps, 2x4), warp tile 64x32, m16n8k16 bf16,
// cp.async 2-stage double buffer, k-chunk 32.
// ---------------------------------------------------------------------------
__global__ void __launch_bounds__(256) gemm_mma_kernel(
    const __nv_bfloat16* __restrict__ Acat, const __nv_bfloat16* __restrict__ Bcat,
    const float* __restrict__ bias, float* __restrict__ C, int N)
{
    __shared__ __nv_bfloat16 As[2][128][ASTRIDE];
    __shared__ __nv_bfloat16 Bs[2][128][ASTRIDE];

    int t    = threadIdx.x;
    int lane = t & 31;
    int wid  = t >> 5;
    int bm   = blockIdx.y * 128;
    int bn   = blockIdx.x * 128;
    uint32_t sA = smem_u32(As);
    uint32_t sB = smem_u32(Bs);

    int lr = t >> 2;            // load row 0..63 (x2 iters -> 128)
    int lc = (t & 3) << 3;      // bf16 col 0,8,16,24

    float acc[4][4][4];
#pragma unroll
    for (int a = 0; a < 4; a++)
#pragma unroll
        for (int b = 0; b < 4; b++)
#pragma unroll
            for (int c = 0; c < 4; c++) acc[a][b][c] = 0.f;

    int wm = wid >> 2;          // 0..1
    int wn = wid & 3;           // 0..3
    int mb = wm * 64;
    int nb = wn * 32;
    int lrow = lane & 15;
    int lcol = (lane >> 4) << 3;

    const int NK = KCAT / 32;   // 48

    // prologue: stage 0
#pragma unroll
    for (int i = 0; i < 2; i++) {
        int r = lr + 64 * i;
        cp16(sA + (uint32_t)((r) * ASTRIDE + lc) * 2,
             Acat + (size_t)(bm + r) * KCAT + lc);
        cp16(sB + (uint32_t)((r) * ASTRIDE + lc) * 2,
             Bcat + (size_t)(bn + r) * KCAT + lc);
    }
    CP_COMMIT();

    for (int kc = 0; kc < NK; kc++) {
        int st = kc & 1;
        if (kc + 1 < NK) {
            int ns = 1 - st;
#pragma unroll
            for (int i = 0; i < 2; i++) {
                int r = lr + 64 * i;
                cp16(sA + (uint32_t)((ns * 128 + r) * ASTRIDE + lc) * 2,
                     Acat + (size_t)(bm + r) * KCAT + (kc + 1) * 32 + lc);
                cp16(sB + (uint32_t)((ns * 128 + r) * ASTRIDE + lc) * 2,
                     Bcat + (size_t)(bn + r) * KCAT + (kc + 1) * 32 + lc);
            }
            CP_COMMIT();
            CP_WAIT(1);
        } else {
            CP_WAIT(0);
        }
        __syncthreads();

#pragma unroll
        for (int ks = 0; ks < 32; ks += 16) {
            uint32_t av[4][4], bv[2][4];
#pragma unroll
            for (int mt = 0; mt < 4; mt++)
                ldmx4(av[mt], sA + (uint32_t)((st * 128 + mb + mt * 16 + lrow) * ASTRIDE
                                              + ks + lcol) * 2);
#pragma unroll
            for (int pt = 0; pt < 2; pt++)
                ldmx4(bv[pt], sB + (uint32_t)((st * 128 + nb + pt * 16 + lrow) * ASTRIDE
                                              + ks + lcol) * 2);
#pragma unroll
            for (int mt = 0; mt < 4; mt++)
#pragma unroll
                for (int nt = 0; nt < 4; nt++) {
                    uint32_t b0 = bv[nt >> 1][nt & 1];
                    uint32_t b1 = bv[nt >> 1][(nt & 1) + 2];
                    mma16816(acc[mt][nt], av[mt], b0, b1);
                }
        }
        __syncthreads();
    }

    // epilogue: bias + store
    int gr = bm + mb + (lane >> 2);
    int gc = bn + nb + (lane & 3) * 2;
#pragma unroll
    for (int mt = 0; mt < 4; mt++) {
#pragma unroll
        for (int nt = 0; nt < 4; nt++) {
            int row = gr + mt * 16;
            int col = gc + nt * 8;
            float b0 = bias[col], b1 = bias[col + 1];
            float2 v0 = make_float2(acc[mt][nt][0] + b0, acc[mt][nt][1] + b1);
            float2 v1 = make_float2(acc[mt][nt][2] + b0, acc[mt][nt][3] + b1);
            *(float2*)(C + (size_t)row * N + col)       = v0;
            *(float2*)(C + (size_t)(row + 8) * N + col) = v1;
        }
    }
}

// ---------------------------------------------------------------------------
// Flash-style attention over a gathered index list (unchanged from R2)
// ---------------------------------------------------------------------------
__global__ void __launch_bounds__(128) attn_kernel() {
    int x = blockIdx.x;
    int h = blockIdx.y;
    int b = blockIdx.z;

    int seg, tile;
    if      (x < 8)  { seg = 0; tile = x;      }
    else if (x < 16) { seg = 1; tile = x - 8;  }
    else if (x < 24) { seg = 2; tile = x - 16; }
    else             { seg = 3; tile = 0;      }

    int g, base;
    if      (seg == 0) { g = 1024; base = 0; }
    else if (seg == 1) { g = 1024; base = 1024 + (h & 1) * 1024; }
    else if (seg == 2) { g = 1024; base = 3072 + (h & 3) * 1024; }
    else               { g = 128;  base = 7168 + (h & 7) * 128;  }

    int t  = threadIdx.x;
    int gq = g_table[base + tile * 128 + t];

    const float* qp = g_qkv + (size_t)(b * SEQ + gq) * QKVW + h * HD;
    float q[32], acc[32];
#pragma unroll
    for (int i = 0; i < 8; i++) {
        float4 v = *(const float4*)(qp + i * 4);
        q[i * 4 + 0] = v.x * SCALE_L2E;
        q[i * 4 + 1] = v.y * SCALE_L2E;
        q[i * 4 + 2] = v.z * SCALE_L2E;
        q[i * 4 + 3] = v.w * SCALE_L2E;
    }
#pragma unroll
    for (int d = 0; d < 32; d++) acc[d] = 0.f;

    float m = -1e30f;
    float l = 0.f;

    __shared__ float Ks[64][32];
    __shared__ float Vs[64][32];

    for (int kt = 0; kt < g; kt += 64) {
#pragma unroll
        for (int i = 0; i < 4; i++) {
            int f4  = t + 128 * i;
            int row = f4 >> 3;
            int c4  = (f4 & 7) << 2;
            int kidx = g_table[base + kt + row];
            const float* src = g_qkv + (size_t)(b * SEQ + kidx) * QKVW + EMB + h * HD + c4;
            *(float4*)&Ks[row][c4] = *(const float4*)src;
            *(float4*)&Vs[row][c4] = *(const float4*)(src + EMB);
        }
        __syncthreads();

#pragma unroll 2
        for (int j = 0; j < 64; j++) {
            const float4* kr = (const float4*)Ks[j];
            float s0 = 0.f, s1 = 0.f, s2 = 0.f, s3 = 0.f;
#pragma unroll
            for (int i = 0; i < 8; i++) {
                float4 kv = kr[i];
                s0 = fmaf(q[i * 4 + 0], kv.x, s0);
                s1 = fmaf(q[i * 4 + 1], kv.y, s1);
                s2 = fmaf(q[i * 4 + 2], kv.z, s2);
                s3 = fmaf(q[i * 4 + 3], kv.w, s3);
            }
            float s  = (s0 + s1) + (s2 + s3);
            float mn = fmaxf(m, s);
            float p  = ex2f(s - mn);
            if (mn > m) {
                float corr = ex2f(m - mn);
                l *= corr;
#pragma unroll
                for (int d = 0; d < 32; d++) acc[d] *= corr;
                m = mn;
            }
            l += p;
            const float4* vr = (const float4*)Vs[j];
#pragma unroll
            for (int i = 0; i < 8; i++) {
                float4 vv = vr[i];
                acc[i * 4 + 0] = fmaf(p, vv.x, acc[i * 4 + 0]);
                acc[i * 4 + 1] = fmaf(p, vv.y, acc[i * 4 + 1]);
                acc[i * 4 + 2] = fmaf(p, vv.z, acc[i * 4 + 2]);
                acc[i * 4 + 3] = fmaf(p, vv.w, acc[i * 4 + 3]);
            }
        }
        __syncthreads();
    }

    float inv = 1.0f / l;
    float* op = g_o + (size_t)(b * SEQ + gq) * EMB + h * HD;
#pragma unroll
    for (int i = 0; i < 8; i++) {
        float4 ov;
        ov.x = acc[i * 4 + 0] * inv;
        ov.y = acc[i * 4 + 1] * inv;
        ov.z = acc[i * 4 + 2] * inv;
        ov.w = acc[i * 4 + 3] * inv;
        *(float4*)(op + i * 4) = ov;
    }
}

// ---------------------------------------------------------------------------
// Launch
// ---------------------------------------------------------------------------
extern "C" void kernel_launch(void* const* d_in, const int* in_sizes, int n_in,
                              void* d_out, int out_size) {
    const float* x     = (const float*)d_in[0];
    const float* w_qkv = (const float*)d_in[1];
    const float* b_qkv = (const float*)d_in[2];
    const float* w_out = (const float*)d_in[3];
    const float* b_out = (const float*)d_in[4];
    float* out = (float*)d_out;

    float *qkv_ptr = nullptr, *o_ptr = nullptr;
    __nv_bfloat16 *acat, *ocat, *bq, *bo;
    cudaGetSymbolAddress((void**)&qkv_ptr, g_qkv);
    cudaGetSymbolAddress((void**)&o_ptr,   g_o);
    cudaGetSymbolAddress((void**)&acat, g_acat);
    cudaGetSymbolAddress((void**)&ocat, g_ocat);
    cudaGetSymbolAddress((void**)&bq,   g_bq);
    cudaGetSymbolAddress((void**)&bo,   g_bo);

    // 1. index tables
    build_table_kernel<<<4, 1024>>>();

    // 2. input/weight splits into concat layout
    split_cat_kernel<<<(MROWS * EMB) / (4 * 256), 256>>>(x, acat);
    {
        dim3 g1(QKVW / 32, EMB / 32);
        transpose_split_cat_kernel<<<g1, dim3(32, 8)>>>(w_qkv, bq, QKVW);
        dim3 g2(EMB / 32, EMB / 32);
        transpose_split_cat_kernel<<<g2, dim3(32, 8)>>>(w_out, bo, EMB);
    }

    // 3. qkv projection (HMMA): (16384x1536cat)·(1536x1536cat)^T + b
    {
        dim3 grid(QKVW / 128, MROWS / 128);
        gemm_mma_kernel<<<grid, 256>>>(acat, bq, b_qkv, qkv_ptr, QKVW);
    }

    // 4. zero attention scratch, run attention
    zero_kernel<<<(MROWS * EMB) / (4 * 256), 256>>>();
    {
        dim3 grid(25, NH, BATCH);
        attn_kernel<<<grid, 128>>>();
    }

    // 5. split attention output, output projection (HMMA) -> d_out
    split_cat_kernel<<<(MROWS * EMB) / (4 * 256), 256>>>(o_ptr, ocat);
    {
        dim3 grid(EMB / 128, MROWS / 128);
        gemm_mma_kernel<<<grid, 256>>>(ocat, bo, b_out, out, EMB);
    }
}

// round 10
// speedup vs baseline: 2.2590x; 1.5722x over previous
// R9: attention restructured to 64-key tiles — halves S/P register arrays
// (~190→~130 regs, no spills) and smem (41K→20K). Same validated HMMA
// conventions as R6 GEMM (1069us pass) and R7 design. De-risks the repeated
// container failures (R7/R8) whether cause was resource pressure or flake.
#include <cuda_runtime.h>
#include <cuda_bf16.h>
#include <cstdint>

#define SEQ   8192
#define BATCH 2
#define EMB   512
#define NH    16
#define HD    32
#define QKVW  1536
#define MROWS (BATCH * SEQ)          // 16384
#define KCAT  1536                   // 3 x 512 split terms
#define ASTRIDE 40                   // padded smem row (bf16 elems)

#define SCALE_L2E (0.17677669529663687f * 1.44269504088896340f)

__device__ float g_qkv[MROWS * QKVW];
__device__ float g_o[MROWS * EMB];
__device__ int   g_table[SEQ];

__device__ __nv_bfloat16 g_acat[MROWS * KCAT];
__device__ __nv_bfloat16 g_ocat[MROWS * KCAT];
__device__ __nv_bfloat16 g_bq[QKVW * KCAT];
__device__ __nv_bfloat16 g_bo[EMB * KCAT];

static __device__ __forceinline__ float ex2f(float x) {
    float y; asm("ex2.approx.f32 %0, %1;" : "=f"(y) : "f"(x)); return y;
}

static __device__ __forceinline__ uint32_t smem_u32(const void* p) {
    uint32_t a;
    asm("{ .reg .u64 t; cvta.to.shared.u64 t, %1; cvt.u32.u64 %0, t; }" : "=r"(a) : "l"(p));
    return a;
}

static __device__ __forceinline__ void cp16(uint32_t s, const void* g) {
    asm volatile("cp.async.cg.shared.global [%0], [%1], 16;" :: "r"(s), "l"(g));
}
#define CP_COMMIT() asm volatile("cp.async.commit_group;" ::: "memory")
#define CP_WAIT(n)  asm volatile("cp.async.wait_group %0;" :: "n"(n) : "memory")

static __device__ __forceinline__ void ldmx4(uint32_t* r, uint32_t addr) {
    asm volatile("ldmatrix.sync.aligned.m8n8.x4.shared.b16 {%0,%1,%2,%3}, [%4];"
                 : "=r"(r[0]), "=r"(r[1]), "=r"(r[2]), "=r"(r[3]) : "r"(addr));
}
static __device__ __forceinline__ void ldmx4t(uint32_t* r, uint32_t addr) {
    asm volatile("ldmatrix.sync.aligned.m8n8.x4.trans.shared.b16 {%0,%1,%2,%3}, [%4];"
                 : "=r"(r[0]), "=r"(r[1]), "=r"(r[2]), "=r"(r[3]) : "r"(addr));
}

static __device__ __forceinline__ void mma16816(float* c, const uint32_t* a,
                                                uint32_t b0, uint32_t b1) {
    asm volatile(
        "mma.sync.aligned.m16n8k16.row.col.f32.bf16.bf16.f32 "
        "{%0,%1,%2,%3}, {%4,%5,%6,%7}, {%8,%9}, {%0,%1,%2,%3};"
        : "+f"(c[0]), "+f"(c[1]), "+f"(c[2]), "+f"(c[3])
        : "r"(a[0]), "r"(a[1]), "r"(a[2]), "r"(a[3]), "r"(b0), "r"(b1));
}

static __device__ __forceinline__ uint32_t packbf2(float a, float b) {
    __nv_bfloat162 h = __float22bfloat162_rn(make_float2(a, b));
    return *(uint32_t*)&h;
}

// ---------------------------------------------------------------------------
// Hilbert index-table build (unchanged)
// ---------------------------------------------------------------------------
__device__ __forceinline__ int hilbert_lin(int side, int d) {
    int x = 0, y = 0, t = d;
    for (int s = 1; s < side; s <<= 1) {
        int rx = (t >> 1) & 1;
        int ry = (t ^ rx) & 1;
        if (ry == 0) {
            if (rx == 1) { x = s - 1 - x; y = s - 1 - y; }
            int tmp = x; x = y; y = tmp;
        }
        x += s * rx;
        y += s * ry;
        t >>= 2;
    }
    return y * side + x;
}

__global__ void build_table_kernel() {
    const int posA[4]  = {0, 1024, 3072, 7168};
    const int LA[4]    = {1024, 2048, 4096, 1024};
    const int rA[4]    = {1, 2, 4, 8};
    const int sideA[4] = {32, 64, 64, 32};

    int seg = blockIdx.x;
    int pos = posA[seg], L = LA[seg], r = rA[seg], side = sideA[seg];
    int side2 = side * side;
    int g = L / r;
    int t = threadIdx.x;
    int chunk = side2 >> 10;

    int lin[4];
    int cnt = 0;
    for (int c = 0; c < chunk; c++) {
        lin[c] = hilbert_lin(side, t * chunk + c);
        if (lin[c] < L) cnt++;
    }

    __shared__ int sc[1024];
    sc[t] = cnt;
    __syncthreads();
    for (int off = 1; off < 1024; off <<= 1) {
        int v = (t >= off) ? sc[t - off] : 0;
        __syncthreads();
        sc[t] += v;
        __syncthreads();
    }
    int i = sc[t] - cnt;

    for (int c = 0; c < chunk; c++) {
        if (lin[c] < L) {
            int res = i % r;
            int j   = i / r;
            g_table[pos + res * g + j] = pos + lin[c];
            i++;
        }
    }
}

// ---------------------------------------------------------------------------
// fp32 [M][512] -> concat bf16 [M][1536] = [hi | hi | lo]
// ---------------------------------------------------------------------------
__global__ void split_cat_kernel(const float* __restrict__ in,
                                 __nv_bfloat16* __restrict__ cat) {
    int i4 = (blockIdx.x * 256 + threadIdx.x) * 4;
    int m = i4 >> 9;
    int j = i4 & 511;
    float4 v = *(const float4*)(in + i4);

    __nv_bfloat162 h0, h1, l0, l1;
    h0.x = __float2bfloat16(v.x);  h0.y = __float2bfloat16(v.y);
    h1.x = __float2bfloat16(v.z);  h1.y = __float2bfloat16(v.w);
    l0.x = __float2bfloat16(v.x - __bfloat162float(h0.x));
    l0.y = __float2bfloat16(v.y - __bfloat162float(h0.y));
    l1.x = __float2bfloat16(v.z - __bfloat162float(h1.x));
    l1.y = __float2bfloat16(v.w - __bfloat162float(h1.y));

    __nv_bfloat16* row = cat + (size_t)m * KCAT;
    *(__nv_bfloat162*)(row + j)          = h0;
    *(__nv_bfloat162*)(row + j + 2)      = h1;
    *(__nv_bfloat162*)(row + 512 + j)    = h0;
    *(__nv_bfloat162*)(row + 512 + j + 2)= h1;
    *(__nv_bfloat162*)(row + 1024 + j)   = l0;
    *(__nv_bfloat162*)(row + 1024 + j + 2)= l1;
}

// ---------------------------------------------------------------------------
// fp32 weight [K=512][N] -> transposed concat bf16 [N][1536] = [hi | lo | hi]
// ---------------------------------------------------------------------------
__global__ void transpose_split_cat_kernel(const float* __restrict__ in,
                                           __nv_bfloat16* __restrict__ cat, int N) {
    __shared__ float tile[32][33];
    int n0 = blockIdx.x * 32, k0 = blockIdx.y * 32;
    int tx = threadIdx.x, ty = threadIdx.y;
#pragma unroll
    for (int i = 0; i < 32; i += 8)
        tile[ty + i][tx] = in[(size_t)(k0 + ty + i) * N + n0 + tx];
    __syncthreads();
#pragma unroll
    for (int i = 0; i < 32; i += 8) {
        float v = tile[tx][ty + i];
        __nv_bfloat16 h = __float2bfloat16(v);
        __nv_bfloat16 l = __float2bfloat16(v - __bfloat162float(h));
        size_t o = (size_t)(n0 + ty + i) * KCAT + k0 + tx;
        cat[o]        = h;
        cat[o + 512]  = l;
        cat[o + 1024] = h;
    }
}

__global__ void zero_kernel() {
    int i = (blockIdx.x * 256 + threadIdx.x) * 4;
    *(float4*)(g_o + i) = make_float4(0.f, 0.f, 0.f, 0.f);
}

// ---------------------------------------------------------------------------
// HMMA GEMM (unchanged from R6)
// ---------------------------------------------------------------------------
__global__ void __launch_bounds__(256) gemm_mma_kernel(
    const __nv_bfloat16* __restrict__ Acat, const __nv_bfloat16* __restrict__ Bcat,
    const float* __restrict__ bias, float* __restrict__ C, int N)
{
    __shared__ __nv_bfloat16 As[2][128][ASTRIDE];
    __shared__ __nv_bfloat16 Bs[2][128][ASTRIDE];

    int t    = threadIdx.x;
    int lane = t & 31;
    int wid  = t >> 5;
    int bm   = blockIdx.y * 128;
    int bn   = blockIdx.x * 128;
    uint32_t sA = smem_u32(As);
    uint32_t sB = smem_u32(Bs);

    int lr = t >> 2;
    int lc = (t & 3) << 3;

    float acc[4][4][4];
#pragma unroll
    for (int a = 0; a < 4; a++)
#pragma unroll
        for (int b = 0; b < 4; b++)
#pragma unroll
            for (int c = 0; c < 4; c++) acc[a][b][c] = 0.f;

    int wm = wid >> 2;
    int wn = wid & 3;
    int mb = wm * 64;
    int nb = wn * 32;
    int lrow = lane & 15;
    int lcol = (lane >> 4) << 3;

    const int NK = KCAT / 32;

#pragma unroll
    for (int i = 0; i < 2; i++) {
        int r = lr + 64 * i;
        cp16(sA + (uint32_t)((r) * ASTRIDE + lc) * 2,
             Acat + (size_t)(bm + r) * KCAT + lc);
        cp16(sB + (uint32_t)((r) * ASTRIDE + lc) * 2,
             Bcat + (size_t)(bn + r) * KCAT + lc);
    }
    CP_COMMIT();

    for (int kc = 0; kc < NK; kc++) {
        int st = kc & 1;
        if (kc + 1 < NK) {
            int ns = 1 - st;
#pragma unroll
            for (int i = 0; i < 2; i++) {
                int r = lr + 64 * i;
                cp16(sA + (uint32_t)((ns * 128 + r) * ASTRIDE + lc) * 2,
                     Acat + (size_t)(bm + r) * KCAT + (kc + 1) * 32 + lc);
                cp16(sB + (uint32_t)((ns * 128 + r) * ASTRIDE + lc) * 2,
                     Bcat + (size_t)(bn + r) * KCAT + (kc + 1) * 32 + lc);
            }
            CP_COMMIT();
            CP_WAIT(1);
        } else {
            CP_WAIT(0);
        }
        __syncthreads();

#pragma unroll
        for (int ks = 0; ks < 32; ks += 16) {
            uint32_t av[4][4], bv[2][4];
#pragma unroll
            for (int mt = 0; mt < 4; mt++)
                ldmx4(av[mt], sA + (uint32_t)((st * 128 + mb + mt * 16 + lrow) * ASTRIDE
                                              + ks + lcol) * 2);
#pragma unroll
            for (int pt = 0; pt < 2; pt++)
                ldmx4(bv[pt], sB + (uint32_t)((st * 128 + nb + pt * 16 + lrow) * ASTRIDE
                                              + ks + lcol) * 2);
#pragma unroll
            for (int mt = 0; mt < 4; mt++)
#pragma unroll
                for (int nt = 0; nt < 4; nt++) {
                    uint32_t b0 = bv[nt >> 1][nt & 1];
                    uint32_t b1 = bv[nt >> 1][(nt & 1) + 2];
                    mma16816(acc[mt][nt], av[mt], b0, b1);
                }
        }
        __syncthreads();
    }

    int gr = bm + mb + (lane >> 2);
    int gc = bn + nb + (lane & 3) * 2;
#pragma unroll
    for (int mt = 0; mt < 4; mt++) {
#pragma unroll
        for (int nt = 0; nt < 4; nt++) {
            int row = gr + mt * 16;
            int col = gc + nt * 8;
            float b0 = bias[col], b1 = bias[col + 1];
            float2 v0 = make_float2(acc[mt][nt][0] + b0, acc[mt][nt][1] + b1);
            float2 v1 = make_float2(acc[mt][nt][2] + b0, acc[mt][nt][3] + b1);
            *(float2*)(C + (size_t)row * N + col)       = v0;
            *(float2*)(C + (size_t)(row + 8) * N + col) = v1;
        }
    }
}

// ---------------------------------------------------------------------------
// HMMA flash attention, 64-key tiles.
// grid (25,16,2), 256 thr (8 warps x 16 q-rows = 128 q-rows per block).
// smem: sm[4][64][40] — per tile: Khi/Klo/Vhi/Vlo. Q staged once via the same
// storage viewed as hi=[128][40] (sm[0..1]) and lo=[128][40] (sm[2..3]).
// S = qh·kh + qh·kl + ql·kh (fp32 acc, 8 frags); online softmax in regs;
// O += ph·vh + ph·vl + pl·vh, P-frags repacked from S acc regs.
// ---------------------------------------------------------------------------
__device__ __forceinline__ void load_split16(const float* src, float scale,
                                             __nv_bfloat16* dhi, __nv_bfloat16* dlo) {
#pragma unroll
    for (int i = 0; i < 4; i++) {
        float4 v = ((const float4*)src)[i];
        v.x *= scale; v.y *= scale; v.z *= scale; v.w *= scale;
        __nv_bfloat162 h0, h1, l0, l1;
        h0.x = __float2bfloat16(v.x);  h0.y = __float2bfloat16(v.y);
        h1.x = __float2bfloat16(v.z);  h1.y = __float2bfloat16(v.w);
        l0.x = __float2bfloat16(v.x - __bfloat162float(h0.x));
        l0.y = __float2bfloat16(v.y - __bfloat162float(h0.y));
        l1.x = __float2bfloat16(v.z - __bfloat162float(h1.x));
        l1.y = __float2bfloat16(v.w - __bfloat162float(h1.y));
        ((__nv_bfloat162*)dhi)[i * 2]     = h0;
        ((__nv_bfloat162*)dhi)[i * 2 + 1] = h1;
        ((__nv_bfloat162*)dlo)[i * 2]     = l0;
        ((__nv_bfloat162*)dlo)[i * 2 + 1] = l1;
    }
}

__global__ void __launch_bounds__(256) attn_mma_kernel() {
    __shared__ __nv_bfloat16 sm[4][64][ASTRIDE];   // 20480 B

    int x = blockIdx.x, h = blockIdx.y, b = blockIdx.z;
    int seg, tile;
    if      (x < 8)  { seg = 0; tile = x;      }
    else if (x < 16) { seg = 1; tile = x - 8;  }
    else if (x < 24) { seg = 2; tile = x - 16; }
    else             { seg = 3; tile = 0;      }
    int g, base;
    if      (seg == 0) { g = 1024; base = 0; }
    else if (seg == 1) { g = 1024; base = 1024 + (h & 1) * 1024; }
    else if (seg == 2) { g = 1024; base = 3072 + (h & 3) * 1024; }
    else               { g = 128;  base = 7168 + (h & 7) * 128;  }

    int t = threadIdx.x, lane = t & 31, w = t >> 5;
    uint32_t uKhi = smem_u32(sm[0]);
    uint32_t uKlo = smem_u32(sm[1]);
    uint32_t uVhi = smem_u32(sm[2]);
    uint32_t uVlo = smem_u32(sm[3]);
    int qbase = base + tile * 128;

    // ---- stage all 128 Q rows: hi in sm[0..1], lo in sm[2..3] ----
    {
        int fr = t >> 1, fh = t & 1;
        int gq = g_table[qbase + fr];
        const float* qp = g_qkv + (size_t)(b * SEQ + gq) * QKVW + h * HD + fh * 16;
        __nv_bfloat16* qhi = &((__nv_bfloat16(*)[ASTRIDE])sm[0])[fr][fh * 16];
        __nv_bfloat16* qlo = &((__nv_bfloat16(*)[ASTRIDE])sm[2])[fr][fh * 16];
        load_split16(qp, SCALE_L2E, qhi, qlo);
    }
    __syncthreads();
    uint32_t aqh[2][4], aql[2][4];
    {
        int row = w * 16 + (lane & 15);
        int col = (lane >> 4) << 3;
#pragma unroll
        for (int ks = 0; ks < 2; ks++) {
            ldmx4(aqh[ks], uKhi + (uint32_t)(row * ASTRIDE + ks * 16 + col) * 2);
            ldmx4(aql[ks], uVhi + (uint32_t)(row * ASTRIDE + ks * 16 + col) * 2);
        }
    }
    __syncthreads();

    float m0 = -1e30f, m8 = -1e30f, l0 = 0.f, l8 = 0.f;
    float O[4][4];
#pragma unroll
    for (int i = 0; i < 4; i++)
#pragma unroll
        for (int j = 0; j < 4; j++) O[i][j] = 0.f;

    for (int kt = 0; kt < g; kt += 64) {
        // ---- fill 64-row K/V hi/lo tiles: one load_split16 per thread ----
        {
            int fr2 = t >> 2, fq = t & 3;
            int kidx = g_table[base + kt + fr2];
            const float* kp = g_qkv + (size_t)(b * SEQ + kidx) * QKVW + EMB
                            + h * HD + (fq & 1) * 16;
            if (fq < 2)
                load_split16(kp, 1.0f, &sm[0][fr2][(fq & 1) * 16], &sm[1][fr2][(fq & 1) * 16]);
            else
                load_split16(kp + EMB, 1.0f, &sm[2][fr2][(fq & 1) * 16], &sm[3][fr2][(fq & 1) * 16]);
        }
        __syncthreads();

        // ---- S = Q·K^T (3 split terms), 8 n-frags ----
        float S[8][4];
#pragma unroll
        for (int i = 0; i < 8; i++)
#pragma unroll
            for (int j = 0; j < 4; j++) S[i][j] = 0.f;

        {
            int krow = lane & 15;
            int kcol = (lane >> 4) << 3;
#pragma unroll
            for (int kg = 0; kg < 4; kg++) {
                uint32_t bkh[2][4], bkl[2][4];
                uint32_t rbase = (uint32_t)((kg * 16 + krow) * ASTRIDE + kcol) * 2;
                ldmx4(bkh[0], uKhi + rbase);
                ldmx4(bkh[1], uKhi + rbase + 32);
                ldmx4(bkl[0], uKlo + rbase);
                ldmx4(bkl[1], uKlo + rbase + 32);
#pragma unroll
                for (int ks = 0; ks < 2; ks++) {
                    mma16816(S[2 * kg],     aqh[ks], bkh[ks][0], bkh[ks][2]);
                    mma16816(S[2 * kg + 1], aqh[ks], bkh[ks][1], bkh[ks][3]);
                    mma16816(S[2 * kg],     aqh[ks], bkl[ks][0], bkl[ks][2]);
                    mma16816(S[2 * kg + 1], aqh[ks], bkl[ks][1], bkl[ks][3]);
                    mma16816(S[2 * kg],     aql[ks], bkh[ks][0], bkh[ks][2]);
                    mma16816(S[2 * kg + 1], aql[ks], bkh[ks][1], bkh[ks][3]);
                }
            }
        }

        // ---- online softmax (rows lane>>2 and +8) ----
        float mx0 = -1e30f, mx8 = -1e30f;
#pragma unroll
        for (int nf = 0; nf < 8; nf++) {
            mx0 = fmaxf(mx0, fmaxf(S[nf][0], S[nf][1]));
            mx8 = fmaxf(mx8, fmaxf(S[nf][2], S[nf][3]));
        }
        mx0 = fmaxf(mx0, __shfl_xor_sync(0xffffffffu, mx0, 1));
        mx0 = fmaxf(mx0, __shfl_xor_sync(0xffffffffu, mx0, 2));
        mx8 = fmaxf(mx8, __shfl_xor_sync(0xffffffffu, mx8, 1));
        mx8 = fmaxf(mx8, __shfl_xor_sync(0xffffffffu, mx8, 2));

        float mn0 = fmaxf(m0, mx0), mn8 = fmaxf(m8, mx8);
        float c0 = ex2f(m0 - mn0), c8 = ex2f(m8 - mn8);
        m0 = mn0; m8 = mn8;

        float sum0 = 0.f, sum8 = 0.f;
#pragma unroll
        for (int nf = 0; nf < 8; nf++) {
            S[nf][0] = ex2f(S[nf][0] - mn0);
            S[nf][1] = ex2f(S[nf][1] - mn0);
            S[nf][2] = ex2f(S[nf][2] - mn8);
            S[nf][3] = ex2f(S[nf][3] - mn8);
            sum0 += S[nf][0] + S[nf][1];
            sum8 += S[nf][2] + S[nf][3];
        }
        sum0 += __shfl_xor_sync(0xffffffffu, sum0, 1);
        sum0 += __shfl_xor_sync(0xffffffffu, sum0, 2);
        sum8 += __shfl_xor_sync(0xffffffffu, sum8, 1);
        sum8 += __shfl_xor_sync(0xffffffffu, sum8, 2);
        l0 = l0 * c0 + sum0;
        l8 = l8 * c8 + sum8;
#pragma unroll
        for (int nf = 0; nf < 4; nf++) {
            O[nf][0] *= c0; O[nf][1] *= c0;
            O[nf][2] *= c8; O[nf][3] *= c8;
        }

        // ---- P hi/lo frags from S regs ----
        uint32_t ph01[8], ph23[8], pl01[8], pl23[8];
#pragma unroll
        for (int nf = 0; nf < 8; nf++) {
            uint32_t h01 = packbf2(S[nf][0], S[nf][1]);
            uint32_t h23 = packbf2(S[nf][2], S[nf][3]);
            __nv_bfloat162 hb01 = *(__nv_bfloat162*)&h01;
            __nv_bfloat162 hb23 = *(__nv_bfloat162*)&h23;
            ph01[nf] = h01; ph23[nf] = h23;
            pl01[nf] = packbf2(S[nf][0] - __bfloat162float(hb01.x),
                               S[nf][1] - __bfloat162float(hb01.y));
            pl23[nf] = packbf2(S[nf][2] - __bfloat162float(hb23.x),
                               S[nf][3] - __bfloat162float(hb23.y));
        }

        // ---- O += P·V (3 split terms) ----
        {
            int lr  = lane & 7;
            int sel = lane >> 3;
            int vro = (sel & 1) * 8 + lr;
            int vco = (sel >> 1) * 8;
#pragma unroll
            for (int kk = 0; kk < 4; kk++) {
                uint32_t aphi[4] = {ph01[2 * kk], ph23[2 * kk], ph01[2 * kk + 1], ph23[2 * kk + 1]};
                uint32_t aplo[4] = {pl01[2 * kk], pl23[2 * kk], pl01[2 * kk + 1], pl23[2 * kk + 1]};
                uint32_t bvh[2][4], bvl[2][4];
                uint32_t rb = (uint32_t)((kk * 16 + vro) * ASTRIDE + vco) * 2;
                ldmx4t(bvh[0], uVhi + rb);
                ldmx4t(bvh[1], uVhi + rb + 32);
                ldmx4t(bvl[0], uVlo + rb);
                ldmx4t(bvl[1], uVlo + rb + 32);
#pragma unroll
                for (int dg = 0; dg < 2; dg++) {
                    mma16816(O[2 * dg],     aphi, bvh[dg][0], bvh[dg][1]);
                    mma16816(O[2 * dg + 1], aphi, bvh[dg][2], bvh[dg][3]);
                    mma16816(O[2 * dg],     aplo, bvh[dg][0], bvh[dg][1]);
                    mma16816(O[2 * dg + 1], aplo, bvh[dg][2], bvh[dg][3]);
                    mma16816(O[2 * dg],     aphi, bvl[dg][0], bvl[dg][1]);
                    mma16816(O[2 * dg + 1], aphi, bvl[dg][2], bvl[dg][3]);
                }
            }
        }
        __syncthreads();
    }

    // ---- epilogue: normalize, scatter to g_o ----
    float inv0 = 1.0f / l0, inv8 = 1.0f / l8;
    int r0  = w * 16 + (lane >> 2);
    int gq0 = g_table[qbase + r0];
    int gq8 = g_table[qbase + r0 + 8];
    int c   = (lane & 3) * 2;
    float* o0 = g_o + (size_t)(b * SEQ + gq0) * EMB + h * HD + c;
    float* o8 = g_o + (size_t)(b * SEQ + gq8) * EMB + h * HD + c;
#pragma unroll
    for (int nf = 0; nf < 4; nf++) {
        *(float2*)(o0 + nf * 8) = make_float2(O[nf][0] * inv0, O[nf][1] * inv0);
        *(float2*)(o8 + nf * 8) = make_float2(O[nf][2] * inv8, O[nf][3] * inv8);
    }
}

// ---------------------------------------------------------------------------
// Launch
// ---------------------------------------------------------------------------
extern "C" void kernel_launch(void* const* d_in, const int* in_sizes, int n_in,
                              void* d_out, int out_size) {
    const float* x     = (const float*)d_in[0];
    const float* w_qkv = (const float*)d_in[1];
    const float* b_qkv = (const float*)d_in[2];
    const float* w_out = (const float*)d_in[3];
    const float* b_out = (const float*)d_in[4];
    float* out = (float*)d_out;

    float *qkv_ptr = nullptr, *o_ptr = nullptr;
    __nv_bfloat16 *acat, *ocat, *bq, *bo;
    cudaGetSymbolAddress((void**)&qkv_ptr, g_qkv);
    cudaGetSymbolAddress((void**)&o_ptr,   g_o);
    cudaGetSymbolAddress((void**)&acat, g_acat);
    cudaGetSymbolAddress((void**)&ocat, g_ocat);
    cudaGetSymbolAddress((void**)&bq,   g_bq);
    cudaGetSymbolAddress((void**)&bo,   g_bo);

    build_table_kernel<<<4, 1024>>>();

    split_cat_kernel<<<(MROWS * EMB) / (4 * 256), 256>>>(x, acat);
    {
        dim3 g1(QKVW / 32, EMB / 32);
        transpose_split_cat_kernel<<<g1, dim3(32, 8)>>>(w_qkv, bq, QKVW);
        dim3 g2(EMB / 32, EMB / 32);
        transpose_split_cat_kernel<<<g2, dim3(32, 8)>>>(w_out, bo, EMB);
    }

    {
        dim3 grid(QKVW / 128, MROWS / 128);
        gemm_mma_kernel<<<grid, 256>>>(acat, bq, b_qkv, qkv_ptr, QKVW);
    }

    zero_kernel<<<(MROWS * EMB) / (4 * 256), 256>>>();
    {
        dim3 grid(25, NH, BATCH);
        attn_mma_kernel<<<grid, 256>>>();
    }

    split_cat_kernel<<<(MROWS * EMB) / (4 * 256), 256>>>(o_ptr, ocat);
    {
        dim3 grid(EMB / 128, MROWS / 128);
        gemm_mma_kernel<<<grid, 256>>>(ocat, bo, b_out, out, EMB);
    }
}